// round 3
// baseline (speedup 1.0000x reference)
#include <cuda_runtime.h>
#include <cstdint>

#define FULLMASK 0xffffffffu

// Precomputed per-group propagator M_g = (I + dt*A + dt^2/2 * A^2)^4, A = J - R + (trR/dg) I
__device__ float g_M[8][32][32];

// ---------------------------------------------------------------------------
// Kernel A: build M_g. 8 blocks of 32x32 threads. Cost ~ microseconds.
// ---------------------------------------------------------------------------
__global__ void build_M_kernel(const float* __restrict__ U,
                               const float* __restrict__ V,
                               const float* __restrict__ S) {
    const int g = blockIdx.x;
    const int e = threadIdx.x;  // column
    const int d = threadIdx.y;  // row
    __shared__ float Us[32][16], Vs[32][16], Ss[32][16];
    __shared__ float As[32][32], Bs[32][32], Cs[32][32];
    __shared__ float trS;

    if (e < 16) {
        int idx = (g * 32 + d) * 16 + e;
        Us[d][e] = U[idx];
        Vs[d][e] = V[idx];
        Ss[d][e] = S[idx];
    }
    if (d == 0 && e == 0) trS = 0.f;
    __syncthreads();

    if (e < 16) atomicAdd(&trS, Ss[d][e] * Ss[d][e]);

    float a = 0.f;
#pragma unroll
    for (int r = 0; r < 16; r++)
        a += Us[d][r] * Vs[e][r] - Vs[d][r] * Us[e][r] - Ss[d][r] * Ss[e][r];
    __syncthreads();                 // trS atomics complete

    if (d == e) a += trS * (1.f / 32.f);
    As[d][e] = a;
    __syncthreads();

    float a2 = 0.f;
#pragma unroll
    for (int m = 0; m < 32; m++) a2 += As[d][m] * As[m][e];
    // P = I + dt*A + (dt^2/2)*A^2 ; dt = 0.1
    float p = ((d == e) ? 1.f : 0.f) + 0.1f * a + 0.005f * a2;
    Bs[d][e] = p;
    __syncthreads();

    float p2 = 0.f;
#pragma unroll
    for (int m = 0; m < 32; m++) p2 += Bs[d][m] * Bs[m][e];
    Cs[d][e] = p2;
    __syncthreads();

    float p4 = 0.f;
#pragma unroll
    for (int m = 0; m < 32; m++) p4 += Cs[d][m] * Cs[m][e];
    g_M[g][d][e] = p4;
}

// ---------------------------------------------------------------------------
// Packed f32x2 helpers (Blackwell)
// ---------------------------------------------------------------------------
__device__ __forceinline__ unsigned long long dup2(float m) {
    unsigned long long r;
    asm("mov.b64 %0, {%1, %1};" : "=l"(r) : "f"(m));
    return r;
}
__device__ __forceinline__ void ffma2(unsigned long long& acc,
                                      unsigned long long a,
                                      unsigned long long b) {
    asm("fma.rn.f32x2 %0, %1, %2, %0;" : "+l"(acc) : "l"(a), "l"(b));
}
__device__ __forceinline__ float2 unpack2(unsigned long long v) {
    float2 r;
    asm("mov.b64 {%0, %1}, %2;" : "=f"(r.x), "=f"(r.y) : "l"(v));
    return r;
}

// ---------------------------------------------------------------------------
// Kernel B: fused groupwise-norm -> Chebyshev(9) along W -> z = M_g * y
// Grid: (4 W-tiles of 128, 8 groups, 256 batch). Block: 512 threads.
// Window = 128 + 2*8 halo = 144 tokens. Recursion fully in registers:
// each thread owns one channel (c = tid>>4) and a 9-token span (s = tid&15);
// span-edge exchange via intra-warp shfl (lanes = (c&1)*16 + s).
// Global Dirichlet semantics: reference zero-pads at EVERY Lhat application,
// so T_k is forced to 0 at out-of-domain positions after every step.
// ---------------------------------------------------------------------------
__global__ __launch_bounds__(512, 2)
void continuous_block_kernel(const float* __restrict__ x,
                             const float* __restrict__ cheb,
                             float* __restrict__ out) {
    constexpr int W = 512, D = 256;
    __shared__ float sm[144 * 36];   // staging (norm, row stride 36) then y (pair rows, stride 68)

    const int tid  = threadIdx.x;
    const int lane = tid & 31;
    const int warp = tid >> 5;
    const int g  = blockIdx.y;
    const int b  = blockIdx.z;
    const int w0 = blockIdx.x * 128;

    const float* xg = x + ((size_t)b * W) * D + g * 32;

    // ---- Phase 1: coalesced load + groupwise layer norm -> sm[p*36 + c] ----
    {
        const int c4 = lane & 7;   // channel quad
        const int tq = lane >> 3;  // token within quad
        for (int sl = warp; sl < 36; sl += 16) {
            int p  = sl * 4 + tq;          // window position 0..143
            int wg = w0 - 8 + p;           // global token
            float4 v = make_float4(0.f, 0.f, 0.f, 0.f);
            if (wg >= 0 && wg < W)
                v = *reinterpret_cast<const float4*>(xg + (size_t)wg * D + c4 * 4);
            float s1 = v.x + v.y + v.z + v.w;
            float s2 = v.x * v.x + v.y * v.y + v.z * v.z + v.w * v.w;
#pragma unroll
            for (int m = 1; m < 8; m <<= 1) {
                s1 += __shfl_xor_sync(FULLMASK, s1, m);
                s2 += __shfl_xor_sync(FULLMASK, s2, m);
            }
            float mu  = s1 * (1.f / 32.f);
            float var = fmaxf(s2 * (1.f / 32.f) - mu * mu, 0.f);
            float rs  = rsqrtf(var + 1e-6f);
            float4 o;
            o.x = (v.x - mu) * rs; o.y = (v.y - mu) * rs;
            o.z = (v.z - mu) * rs; o.w = (v.w - mu) * rs;
            *reinterpret_cast<float4*>(&sm[p * 36 + c4 * 4]) = o;
        }
    }
    __syncthreads();

    // ---- Chebyshev coefficients ----
    float ck[9];
#pragma unroll
    for (int k = 0; k < 9; k++) ck[k] = cheb[g * 9 + k];

    // ---- Phase 1b: gather per-thread span into registers ----
    const int c  = tid >> 4;   // channel 0..31
    const int s  = tid & 15;   // span    0..15
    const int p0 = s * 9;      // first window token of span
    const int gbase = w0 - 8 + p0;   // global token of span start
    // out-of-domain positions exist only in spans 0 / 15 of boundary tiles
    const bool edgeSpan = ((unsigned)gbase >= (unsigned)W) |
                          ((unsigned)(gbase + 8) >= (unsigned)W);
    float t0[9], t1[9], y[9];
#pragma unroll
    for (int j = 0; j < 9; j++) t0[j] = sm[(p0 + j) * 36 + c];

    // ---- Phase 2: T1 = Lhat T0 ; y = c0*T0 + c1*T1 ----
    {
        float lv = __shfl_up_sync(FULLMASK, t0[8], 1);
        float rv = __shfl_down_sync(FULLMASK, t0[0], 1);
        if (s == 0)  lv = 0.f;
        if (s == 15) rv = 0.f;
#pragma unroll
        for (int j = 0; j < 9; j++) {
            float l = (j == 0) ? lv : t0[j - 1];
            float r = (j == 8) ? rv : t0[j + 1];
            t1[j] = -0.5f * (l + r);
        }
        if (edgeSpan) {
#pragma unroll
            for (int j = 0; j < 9; j++)
                if ((unsigned)(gbase + j) >= (unsigned)W) t1[j] = 0.f;
        }
#pragma unroll
        for (int j = 0; j < 9; j++)
            y[j] = ck[0] * t0[j] + ck[1] * t1[j];
    }

    // ---- Recursion k = 2..8: T2 = 2*Lhat(T1) - T0 = -(T1[l]+T1[r]) - T0 ----
#pragma unroll
    for (int k = 2; k <= 8; k++) {
        float lv = __shfl_up_sync(FULLMASK, t1[8], 1);
        float rv = __shfl_down_sync(FULLMASK, t1[0], 1);
        if (s == 0)  lv = 0.f;
        if (s == 15) rv = 0.f;
        float cc   = ck[k];
        float prev = lv;                    // original t1[j-1] (pre-overwrite)
#pragma unroll
        for (int j = 0; j < 9; j++) {
            float cur = t1[j];
            float r   = (j == 8) ? rv : t1[j + 1];
            float nv  = -(prev + r) - t0[j];
            y[j]  = fmaf(cc, nv, y[j]);
            t0[j] = cur;                    // shift: T0 <- T1
            t1[j] = nv;                     // T1 <- T2
            prev  = cur;
        }
        // enforce global Dirichlet: zero T_k outside [0, W) before next step
        if (edgeSpan) {
#pragma unroll
            for (int j = 0; j < 9; j++)
                if ((unsigned)(gbase + j) >= (unsigned)W) t1[j] = 0.f;
        }
    }
    __syncthreads();   // all phase-1b reads done before sm is reused for y

    // ---- Phase 3: store interior y, token-pair interleaved for f32x2 ----
    // layout: sm[pair*68 + 2*d + (pi&1)], pair = pi>>1, pi = p-8 in [0,128)
#pragma unroll
    for (int j = 0; j < 9; j++) {
        int p = p0 + j;
        if (p >= 8 && p < 136) {
            int pi = p - 8;
            sm[(pi >> 1) * 68 + c * 2 + (pi & 1)] = y[j];
        }
    }
    __syncthreads();

    // ---- Phase 4: z = M_g y, two tokens per packed fma.rn.f32x2 ----
    float4 mrow[8];
    {
        const float4* Mr = reinterpret_cast<const float4*>(&g_M[g][lane][0]);
#pragma unroll
        for (int q = 0; q < 8; q++) mrow[q] = Mr[q];
    }
    unsigned long long acc[4] = {0ull, 0ull, 0ull, 0ull};
    const int Pbase = warp * 4;   // 16 warps * 4 pairs = 64 pairs = 128 tokens
#pragma unroll
    for (int dp = 0; dp < 16; dp++) {
        float4 mq = mrow[dp >> 1];
        float m0 = (dp & 1) ? mq.z : mq.x;
        float m1 = (dp & 1) ? mq.w : mq.y;
        unsigned long long m2a = dup2(m0);
        unsigned long long m2b = dup2(m1);
#pragma unroll
        for (int pr = 0; pr < 4; pr++) {
            ulonglong2 yy = *reinterpret_cast<const ulonglong2*>(
                &sm[(Pbase + pr) * 68 + dp * 4]);   // (d=2dp both tokens, d=2dp+1 both tokens)
            ffma2(acc[pr], m2a, yy.x);
            ffma2(acc[pr], m2b, yy.y);
        }
    }
    float* og = out + ((size_t)b * W) * D + g * 32 + lane;
#pragma unroll
    for (int pr = 0; pr < 4; pr++) {
        float2 z = unpack2(acc[pr]);
        int wgl = w0 + 2 * (Pbase + pr);
        og[(size_t)wgl * D]       = z.x;
        og[(size_t)(wgl + 1) * D] = z.y;
    }
}

// ---------------------------------------------------------------------------
// Launch
// ---------------------------------------------------------------------------
extern "C" void kernel_launch(void* const* d_in, const int* in_sizes, int n_in,
                              void* d_out, int out_size) {
    const float* x    = (const float*)d_in[0];
    const float* cheb = (const float*)d_in[1];
    const float* U    = (const float*)d_in[2];
    const float* V    = (const float*)d_in[3];
    const float* S    = (const float*)d_in[4];
    float* out = (float*)d_out;

    build_M_kernel<<<8, dim3(32, 32)>>>(U, V, S);

    dim3 grid(4, 8, 256);   // (W tiles, groups, batch)
    continuous_block_kernel<<<grid, 512>>>(x, cheb, out);
}

// round 5
// speedup vs baseline: 1.8064x; 1.8064x over previous
#include <cuda_runtime.h>
#include <cstdint>

#define FULLMASK 0xffffffffu

// Precomputed tables (built per launch by build_tables_kernel)
__device__ float g_M[8][32][32];      // Heun propagator M = P^4
__device__ float g_taps[8][17];       // interior 17-tap Chebyshev stencil
__device__ float g_eLT[8][16][8];     // left-edge rows, TRANSPOSED [m][i]
__device__ float g_eRT[8][16][8];     // right-edge rows, TRANSPOSED [m][i]

// ---------------------------------------------------------------------------
// Kernel A: build M_g, interior taps, and edge-row matrices. 8 blocks, 32x32.
// ---------------------------------------------------------------------------
__global__ void build_tables_kernel(const float* __restrict__ U,
                                    const float* __restrict__ V,
                                    const float* __restrict__ S,
                                    const float* __restrict__ cheb) {
    const int g = blockIdx.x;
    const int e = threadIdx.x;  // column
    const int d = threadIdx.y;  // row
    __shared__ float Us[32][16], Vs[32][16], Ss[32][16];
    __shared__ float As[32][32], Bs[32][32], Cs[32][32];
    __shared__ float T1s[34][33];      // rows 1..32 live, rows 0/33 = Dirichlet pad
    __shared__ float trS;

    if (e < 16) {
        int idx = (g * 32 + d) * 16 + e;
        Us[d][e] = U[idx];
        Vs[d][e] = V[idx];
        Ss[d][e] = S[idx];
    }
    if (d == 0 && e == 0) trS = 0.f;
    // T1 = Lhat_32 (tridiagonal -0.5 off-diagonals), padded rows zero
    T1s[d + 1][e] = (d == e + 1 || d + 1 == e) ? -0.5f : 0.f;
    if (d == 0) T1s[0][e]  = 0.f;
    if (d == 1) T1s[33][e] = 0.f;
    __syncthreads();

    if (e < 16) atomicAdd(&trS, Ss[d][e] * Ss[d][e]);

    float a = 0.f;
#pragma unroll
    for (int r = 0; r < 16; r++)
        a += Us[d][r] * Vs[e][r] - Vs[d][r] * Us[e][r] - Ss[d][r] * Ss[e][r];
    __syncthreads();                 // trS atomics complete

    if (d == e) a += trS * (1.f / 32.f);
    As[d][e] = a;
    __syncthreads();

    float a2 = 0.f;
#pragma unroll
    for (int m = 0; m < 32; m++) a2 += As[d][m] * As[m][e];
    // P = I + dt*A + (dt^2/2)*A^2 ; dt = 0.1
    float p = ((d == e) ? 1.f : 0.f) + 0.1f * a + 0.005f * a2;
    Bs[d][e] = p;
    __syncthreads();

    float p2 = 0.f;
#pragma unroll
    for (int m = 0; m < 32; m++) p2 += Bs[d][m] * Bs[m][e];
    Cs[d][e] = p2;
    __syncthreads();

    float p4 = 0.f;
#pragma unroll
    for (int m = 0; m < 32; m++) p4 += Cs[d][m] * Cs[m][e];
    g_M[g][d][e] = p4;

    // ---- Chebyshev polynomial of Lhat_32: acc = sum_k c_k T_k ----
    float ck[9];
#pragma unroll
    for (int k = 0; k < 9; k++) ck[k] = cheb[g * 9 + k];

    float t0v = (d == e) ? 1.f : 0.f;          // T0 row element (register)
    float t1v = T1s[d + 1][e];
    float acc = ck[0] * t0v + ck[1] * t1v;
#pragma unroll
    for (int k = 2; k <= 8; k++) {
        // T2 = 2*Lhat*T1 - T0 ; (Lhat*T1)[d][e] = -0.5*(T1[d-1][e] + T1[d+1][e])
        float t2 = -(T1s[d][e] + T1s[d + 2][e]) - t0v;
        acc += ck[k] * t2;
        __syncthreads();             // all reads of T1s done
        T1s[d + 1][e] = t2;
        t0v = t1v;
        t1v = t2;
        __syncthreads();             // writes visible
    }

    // Interior taps: row 12 is pure Toeplitz (paths of length<=8 never hit edges)
    if (d == 12 && e >= 4 && e <= 20) g_taps[g][e - 4] = acc;
    // Edge rows (exact): left rows 0..7 (support cols 0..15), right rows 24..31
    if (d < 8 && e < 16)             g_eLT[g][e][d] = acc;
    if (d >= 24 && e >= 16)          g_eRT[g][e - 16][d - 24] = acc;
}

// ---------------------------------------------------------------------------
// Packed f32x2 helpers
// ---------------------------------------------------------------------------
__device__ __forceinline__ unsigned long long dup2(float m) {
    unsigned long long r;
    asm("mov.b64 %0, {%1, %1};" : "=l"(r) : "f"(m));
    return r;
}
__device__ __forceinline__ void ffma2(unsigned long long& acc,
                                      unsigned long long a,
                                      unsigned long long b) {
    asm("fma.rn.f32x2 %0, %1, %2, %0;" : "+l"(acc) : "l"(a), "l"(b));
}
__device__ __forceinline__ float2 unpack2(unsigned long long v) {
    float2 r;
    asm("mov.b64 {%0, %1}, %2;" : "=f"(r.x), "=f"(r.y) : "l"(v));
    return r;
}
__device__ __forceinline__ unsigned long long pack2(float lo, float hi) {
    unsigned long long r;
    asm("mov.b64 %0, {%1, %2};" : "=l"(r) : "f"(lo), "f"(hi));
    return r;
}

__device__ __forceinline__ float4 ldx(const float* __restrict__ xg, int w0,
                                      int p, int c4) {
    int wg = w0 - 8 + p;
    if ((unsigned)wg < 512u)
        return *reinterpret_cast<const float4*>(xg + (size_t)wg * 256 + c4 * 4);
    return make_float4(0.f, 0.f, 0.f, 0.f);
}

__device__ __forceinline__ void norm_store(float4 v, float* dst) {
    float s1 = v.x + v.y + v.z + v.w;
    float s2 = fmaf(v.x, v.x, fmaf(v.y, v.y, fmaf(v.z, v.z, v.w * v.w)));
#pragma unroll
    for (int m = 1; m < 8; m <<= 1) {
        s1 += __shfl_xor_sync(FULLMASK, s1, m);
        s2 += __shfl_xor_sync(FULLMASK, s2, m);
    }
    float mu  = s1 * (1.f / 32.f);
    float var = fmaxf(s2 * (1.f / 32.f) - mu * mu, 0.f);
    float rs  = rsqrtf(var + 1e-6f);
    float4 o  = make_float4((v.x - mu) * rs, (v.y - mu) * rs,
                            (v.z - mu) * rs, (v.w - mu) * rs);
    *reinterpret_cast<float4*>(dst) = o;
}

// ---------------------------------------------------------------------------
// Kernel B: fused norm -> 17-tap stencil -> z = M_g * y
// Grid (4 tiles of 128 tokens, 8 groups, 256 batch), 512 threads.
// warp = 8-token group (lane = channel); y handoff is warp-local.
// ONE block-wide barrier total.
// ---------------------------------------------------------------------------
__global__ __launch_bounds__(512, 2)
void continuous_block_kernel(const float* __restrict__ x,
                             float* __restrict__ out) {
    constexpr int W = 512, D = 256;
    __shared__ float stage[144 * 36];   // normalized x, [p][c] stride 36
    __shared__ float ybuf[64 * 68];     // y pairs,      [pair][2c+parity] stride 68
    __shared__ float Msw[1024];         // M, XOR-swizzled rows

    const int tid  = threadIdx.x;
    const int lane = tid & 31;
    const int warp = tid >> 5;
    const int g  = blockIdx.y;
    const int b  = blockIdx.z;
    const int w0 = blockIdx.x * 128;

    const float* xg = x + ((size_t)b * W) * D + g * 32;

    // ---- warp 0: stage M into shared, coalesced LDG -> swizzled STS ----
    if (warp == 0) {
        const float4* Mg = reinterpret_cast<const float4*>(&g_M[g][0][0]);
#pragma unroll
        for (int k = 0; k < 8; k++) {
            int f = k * 32 + lane;                 // float4 index 0..255
            float4 v = Mg[f];
            int dd = f >> 3, q = f & 7;
            reinterpret_cast<float4*>(Msw)[dd * 8 + (q ^ (dd & 7))] = v;
        }
    }

    // ---- interior taps (uniform broadcast loads; issued early) ----
    float w17[17];
#pragma unroll
    for (int j = 0; j < 17; j++) w17[j] = g_taps[g][j];

    // ---- Phase 1: load (MLP up-front) + groupwise norm -> stage ----
    {
        const int c4 = lane & 7, tq = lane >> 3;
        const int p0 = warp * 4 + tq;
        const int p1 = (warp + 16) * 4 + tq;
        const bool extra = (warp >= 4 && warp < 8);
        const int p2 = extra ? (28 + warp) * 4 + tq : p0;
        float4 v0 = ldx(xg, w0, p0, c4);
        float4 v1 = ldx(xg, w0, p1, c4);
        float4 v2 = extra ? ldx(xg, w0, p2, c4) : make_float4(0.f, 0.f, 0.f, 0.f);
        norm_store(v0, &stage[p0 * 36 + c4 * 4]);
        norm_store(v1, &stage[p1 * 36 + c4 * 4]);
        if (extra) norm_store(v2, &stage[p2 * 36 + c4 * 4]);
    }
    __syncthreads();   // the ONLY block-wide barrier

    // ---- Phase 2: stencil. warp s covers tokens [w0+8s, w0+8s+8) ----
    const int s = warp;
    const bool leftEdge  = (w0 == 0)   && (s == 0);
    const bool rightEdge = (w0 == 384) && (s == 15);

    float y[8];
#pragma unroll
    for (int t = 0; t < 8; t++) y[t] = 0.f;

    if (!leftEdge && !rightEdge) {
        const int base = (8 * s) * 36 + lane;     // window pos 8s .. 8s+23
#pragma unroll
        for (int jj = 0; jj < 24; jj++) {
            float xv = stage[base + jj * 36];
#pragma unroll
            for (int t = 0; t < 8; t++) {
                int j = jj - t;
                if (j >= 0 && j < 17) y[t] = fmaf(w17[j], xv, y[t]);
            }
        }
    } else {
        // exact boundary rows: y[t] = sum_m E[t][m] * xhat[edge window m]
        const float(*ET)[8] = leftEdge ? g_eLT[g] : g_eRT[g];
        const int mbase = (leftEdge ? 8 : 120) * 36 + lane;
#pragma unroll
        for (int m = 0; m < 16; m++) {
            float xv = stage[mbase + m * 36];
            float4 e0 = reinterpret_cast<const float4*>(ET[m])[0];
            float4 e1 = reinterpret_cast<const float4*>(ET[m])[1];
            y[0] = fmaf(e0.x, xv, y[0]);
            y[1] = fmaf(e0.y, xv, y[1]);
            y[2] = fmaf(e0.z, xv, y[2]);
            y[3] = fmaf(e0.w, xv, y[3]);
            y[4] = fmaf(e1.x, xv, y[4]);
            y[5] = fmaf(e1.y, xv, y[5]);
            y[6] = fmaf(e1.z, xv, y[6]);
            y[7] = fmaf(e1.w, xv, y[7]);
        }
    }

    // ---- Phase 3: warp-local y store, token-pair packed (STS.64, no conflicts) ----
    {
        unsigned long long* yb = reinterpret_cast<unsigned long long*>(ybuf);
#pragma unroll
        for (int pr = 0; pr < 4; pr++)
            yb[(s * 4 + pr) * 34 + lane] = pack2(y[2 * pr], y[2 * pr + 1]);
    }
    __syncwarp();

    // ---- Phase 4: z = M_g y, rows from swizzled shared M, y broadcast reads ----
    float4 mrow[8];
#pragma unroll
    for (int q = 0; q < 8; q++)
        mrow[q] = reinterpret_cast<const float4*>(Msw)[lane * 8 + (q ^ (lane & 7))];

    unsigned long long acc[4] = {0ull, 0ull, 0ull, 0ull};
#pragma unroll
    for (int dp = 0; dp < 16; dp++) {
        float4 mq = mrow[dp >> 1];
        float m0 = (dp & 1) ? mq.z : mq.x;
        float m1 = (dp & 1) ? mq.w : mq.y;
        unsigned long long m2a = dup2(m0);
        unsigned long long m2b = dup2(m1);
#pragma unroll
        for (int pr = 0; pr < 4; pr++) {
            ulonglong2 yy = *reinterpret_cast<const ulonglong2*>(
                &ybuf[(s * 4 + pr) * 68 + dp * 4]);
            ffma2(acc[pr], m2a, yy.x);
            ffma2(acc[pr], m2b, yy.y);
        }
    }

    float* og = out + ((size_t)b * W + w0 + 8 * s) * D + g * 32 + lane;
#pragma unroll
    for (int pr = 0; pr < 4; pr++) {
        float2 z = unpack2(acc[pr]);
        og[(size_t)(2 * pr) * D]     = z.x;
        og[(size_t)(2 * pr + 1) * D] = z.y;
    }
}

// ---------------------------------------------------------------------------
// Launch
// ---------------------------------------------------------------------------
extern "C" void kernel_launch(void* const* d_in, const int* in_sizes, int n_in,
                              void* d_out, int out_size) {
    const float* x    = (const float*)d_in[0];
    const float* cheb = (const float*)d_in[1];
    const float* U    = (const float*)d_in[2];
    const float* V    = (const float*)d_in[3];
    const float* S    = (const float*)d_in[4];
    float* out = (float*)d_out;

    build_tables_kernel<<<8, dim3(32, 32)>>>(U, V, S, cheb);

    dim3 grid(4, 8, 256);   // (W tiles, groups, batch)
    continuous_block_kernel<<<grid, 512>>>(x, out);
}